// round 4
// baseline (speedup 1.0000x reference)
#include <cuda_runtime.h>

// Problem shapes
#define B_ 128
#define S_ 37
#define T_ 2048
#define D_ 256
#define ST_ 8
#define C_ 2
#define MERGED_ 264
#define NF (2*S_)          // 74 features (x ++ mask)
#define TC 128             // time chunk per CTA
#define NCHUNK (T_/TC)     // 16
#define WST_STRIDE 76      // 74 padded to 76 (16B-aligned rows)

// Per-chunk partial reductions (written without atomics -> deterministic)
__device__ float g_px[(size_t)NCHUNK * B_ * NF];
__device__ float g_pm[NCHUNK * B_];
__device__ float g_pt[NCHUNK * B_];
// Transposed weights so per-thread dot products read contiguous rows.
__device__ __align__(16) float g_WsT[D_ * WST_STRIDE];   // [d][f]
__device__ __align__(16) float g_WmT[MERGED_ * MERGED_]; // [n][k]

__device__ __forceinline__ float wred(float v) {
#pragma unroll
    for (int o = 16; o > 0; o >>= 1) v += __shfl_xor_sync(0xffffffffu, v, o);
    return v;
}

// ---------------------------------------------------------------------------
// Stage 0: transpose Ws [74,256] -> WsT [256,76] (zero-padded) and
// Wm [264,264] -> WmT [264,264]. Tiny (~350 KB), runs in <0.5us.
// ---------------------------------------------------------------------------
__global__ __launch_bounds__(256) void stage0(const float* __restrict__ Ws,
                                              const float* __restrict__ Wm) {
    int idx = blockIdx.x * 256 + threadIdx.x;
    if (idx < MERGED_ * MERGED_) {
        int n = idx / MERGED_, k = idx % MERGED_;
        g_WmT[idx] = Wm[k * MERGED_ + n];
    }
    int idx2 = idx - MERGED_ * MERGED_;
    if (idx2 >= 0 && idx2 < D_ * WST_STRIDE) {
        int d = idx2 / WST_STRIDE, f = idx2 % WST_STRIDE;
        g_WsT[idx2] = (f < NF) ? Ws[f * D_ + d] : 0.f;
    }
}

// ---------------------------------------------------------------------------
// Stage 1: HBM-roofline pass over x + sensor_mask (77.6 MB).
// ---------------------------------------------------------------------------
__global__ __launch_bounds__(256) void stage1(const float* __restrict__ x,
                                              const int*   __restrict__ smk,
                                              const float* __restrict__ tm) {
    __shared__ float xs[S_ * TC];
    __shared__ float ms[S_ * TC];
    __shared__ float valid[TC];
    __shared__ float red[8][2];

    const int chunk = blockIdx.x;
    const int b     = blockIdx.y;
    const int t0    = chunk * TC;

    const float* xb = x   + (size_t)b * S_ * T_ + t0;
    const int*   mb = smk + (size_t)b * S_ * T_ + t0;

    for (int idx = threadIdx.x; idx < S_ * (TC / 4); idx += 256) {
        int s = idx / (TC / 4);
        int j = (idx % (TC / 4)) * 4;
        float4 v = *(const float4*)(xb + (size_t)s * T_ + j);
        *(float4*)(xs + s * TC + j) = v;
        int4 m = *(const int4*)(mb + (size_t)s * T_ + j);
        *(float4*)(ms + s * TC + j) =
            make_float4((float)m.x, (float)m.y, (float)m.z, (float)m.w);
    }
    __syncthreads();

    float vf = 0.f, tv = 0.f;
    if (threadIdx.x < TC) {
        const int t = threadIdx.x;
        int nz = 0;
#pragma unroll
        for (int s = 0; s < S_; s++) {
            nz |= (xs[s * TC + t] != 0.f);
            nz |= (ms[s * TC + t] != 0.f);
        }
        vf = nz ? 1.f : 0.f;
        valid[t] = vf;
        tv = vf * tm[(size_t)b * T_ + t0 + t];
    }

    const int w = threadIdx.x >> 5, lane = threadIdx.x & 31;
    float rv = wred(vf), rt = wred(tv);
    if (lane == 0) { red[w][0] = rv; red[w][1] = rt; }
    __syncthreads();   // also makes valid[] visible to all warps
    if (threadIdx.x == 0) {
        float a = 0.f, c = 0.f;
#pragma unroll
        for (int i = 0; i < 8; i++) { a += red[i][0]; c += red[i][1]; }
        g_pm[chunk * B_ + b] = a;
        g_pt[chunk * B_ + b] = c;
    }

    for (int f = w; f < NF; f += 8) {
        const float* src = (f < S_) ? (xs + f * TC) : (ms + (f - S_) * TC);
        float p = 0.f;
#pragma unroll
        for (int j = lane; j < TC; j += 32) p += valid[j] * src[j];
        p = wred(p);
        if (lane == 0) g_px[((size_t)chunk * B_ + b) * NF + f] = p;
    }
}

// ---------------------------------------------------------------------------
// Stage 2: per-batch tiny MLP with row-contiguous (transposed) weights.
// All dot products are streams of independent LDG.128 -> high MLP.
// ---------------------------------------------------------------------------
__global__ __launch_bounds__(288) void stage2(
    const float* __restrict__ stat,
    const float* __restrict__ bs,
    const float* __restrict__ Wt,  const float* __restrict__ bt,
    const float* __restrict__ Wst, const float* __restrict__ bst,
    const float* __restrict__ bm,
    const float* __restrict__ Wc,  const float* __restrict__ bc,
    float* __restrict__ out) {
    __shared__ __align__(16) float xsum[WST_STRIDE];
    __shared__ __align__(16) float comb[MERGED_];
    __shared__ __align__(16) float comb2[MERGED_];
    __shared__ float sden[2];

    const int b = blockIdx.x;
    const int tid = threadIdx.x;

    // Reduce per-chunk partials.
    if (tid < NF) {
        float a = 0.f;
#pragma unroll
        for (int c = 0; c < NCHUNK; c++) a += g_px[((size_t)c * B_ + b) * NF + tid];
        xsum[tid] = a;
    }
    if (tid >= NF && tid < WST_STRIDE) xsum[tid] = 0.f;   // pad
    if (tid == 287) {
        float a = 0.f, t = 0.f;
#pragma unroll
        for (int c = 0; c < NCHUNK; c++) { a += g_pm[c * B_ + b]; t += g_pt[c * B_ + b]; }
        float den = fmaxf(a, 1e-9f);
        sden[0] = den;
        sden[1] = t / den;
    }
    __syncthreads();

    const float den = sden[0], tsc = sden[1];

    // pooled projection: thread tid reads contiguous row WsT[tid][0..75].
    if (tid < D_) {
        const float4* wr = (const float4*)(g_WsT + tid * WST_STRIDE);
        float p0 = 0.f, p1 = 0.f, p2 = 0.f, p3 = 0.f;
#pragma unroll
        for (int i = 0; i < WST_STRIDE / 4; i++) {
            float4 wv = wr[i];
            float4 cv = *(const float4*)(xsum + 4 * i);
            p0 += wv.x * cv.x; p1 += wv.y * cv.y;
            p2 += wv.z * cv.z; p3 += wv.w * cv.w;
        }
        float p = (p0 + p1) + (p2 + p3);
        comb[tid] = p / den + bs[tid] + bt[tid] + tsc * Wt[tid];
    }
    // static embedding (8 dims) on the spare warp.
    if (tid >= 256 && tid < 256 + ST_) {
        const int j = tid - 256;
        float p = bst[j];
#pragma unroll
        for (int i = 0; i < ST_; i++) p += stat[b * ST_ + i] * Wst[i * ST_ + j];
        comb[D_ + j] = p;
    }
    __syncthreads();

    // merge: relu(comb @ Wm + bm); thread tid reads contiguous WmT row.
    if (tid < MERGED_) {
        const float4* wr = (const float4*)(g_WmT + tid * MERGED_);
        float p0 = 0.f, p1 = 0.f, p2 = 0.f, p3 = 0.f;
#pragma unroll
        for (int i = 0; i < MERGED_ / 4; i++) {    // 66 LDG.128
            float4 wv = wr[i];
            float4 cv = *(const float4*)(comb + 4 * i);
            p0 += wv.x * cv.x; p1 += wv.y * cv.y;
            p2 += wv.z * cv.z; p3 += wv.w * cv.w;
        }
        comb2[tid] = fmaxf(((p0 + p1) + (p2 + p3)) + bm[tid], 0.f);
    }
    __syncthreads();

    // classifier: warp 0 -> class 0, warp 1 -> class 1.
    const int w = tid >> 5, lane = tid & 31;
    if (w < C_) {
        float p = 0.f;
#pragma unroll
        for (int i = lane; i < MERGED_; i += 32) p += comb2[i] * Wc[i * C_ + w];
        p = wred(p);
        if (lane == 0) out[b * C_ + w] = p + bc[w];
    }
}

extern "C" void kernel_launch(void* const* d_in, const int* in_sizes, int n_in,
                              void* d_out, int out_size) {
    const float* x   = (const float*)d_in[0];
    const float* st  = (const float*)d_in[1];
    const float* tm  = (const float*)d_in[2];
    const int*   smk = (const int*)  d_in[3];
    const float* Ws  = (const float*)d_in[4];
    const float* bs  = (const float*)d_in[5];
    const float* Wt  = (const float*)d_in[6];
    const float* bt  = (const float*)d_in[7];
    const float* Wst = (const float*)d_in[8];
    const float* bst = (const float*)d_in[9];
    const float* Wm  = (const float*)d_in[10];
    const float* bm  = (const float*)d_in[11];
    const float* Wc  = (const float*)d_in[12];
    const float* bc  = (const float*)d_in[13];

    const int n0 = (MERGED_ * MERGED_ + D_ * WST_STRIDE + 255) / 256;
    stage0<<<n0, 256>>>(Ws, Wm);
    stage1<<<dim3(NCHUNK, B_), 256>>>(x, smk, tm);
    stage2<<<B_, 288>>>(st, bs, Wt, bt, Wst, bst, bm, Wc, bc, (float*)d_out);
}